// round 2
// baseline (speedup 1.0000x reference)
#include <cuda_runtime.h>
#include <math.h>

#define N_IMG   32
#define C_DIM   128
#define K_CL    64
#define S_TOT   12544
#define SC      128
#define NCHUNK  98          // S_TOT / SC
#define SPLIT   9
#define CPB     11          // ceil(NCHUNK / SPLIT)
#define THREADS 256
#define EPSV    1e-12f

#define XS_STRIDE 129
#define LS_STRIDE 129
#define SMEM_BYTES ((C_DIM * XS_STRIDE + K_CL * LS_STRIDE + K_CL * C_DIM) * 4)

// Deterministic per-split partial buffers (no atomics -> no zeroing needed
// between graph replays, bitwise-identical every call).
__device__ float g_vpart[(size_t)N_IMG * SPLIT * K_CL * C_DIM];
__device__ float g_apart[N_IMG * SPLIT * K_CL];

__global__ void __launch_bounds__(THREADS, 1)
netvlad_main(const float* __restrict__ x, const float* __restrict__ convw) {
    extern __shared__ float sm[];
    float* Xs = sm;                              // [128][129]  x tile, stride-129 pad
    float* Ls = Xs + C_DIM * XS_STRIDE;          // [64][129]   logits -> softmax
    float* Ws = Ls + K_CL * LS_STRIDE;           // [64][128]   conv weight

    const int n   = blockIdx.y;
    const int sp  = blockIdx.x;
    const int tid = threadIdx.x;
    const int w   = tid >> 5;     // warp 0..7  -> k = w + 8*j
    const int l   = tid & 31;     // lane       -> s (GEMM1) or c (GEMM2) = l + 32*i

    // Load W (64x128 = 2048 float4)
    {
        const float4* wg  = (const float4*)convw;
        float4*       ws4 = (float4*)Ws;
        #pragma unroll
        for (int r = 0; r < 8; r++) ws4[tid + THREADS * r] = wg[tid + THREADS * r];
    }

    float vacc[8][4];
    #pragma unroll
    for (int j = 0; j < 8; j++)
        #pragma unroll
        for (int i = 0; i < 4; i++) vacc[j][i] = 0.f;
    float asum = 0.f;

    const int chunk0 = sp * CPB;
    const int chunk1 = min(NCHUNK, chunk0 + CPB);

    for (int ch = chunk0; ch < chunk1; ch++) {
        const int s0 = ch * SC;

        // ---- load X chunk: x[n, c, s0:s0+128] -> Xs[c][s] (stride 129) ----
        {
            const float* xb = x + (size_t)n * C_DIM * S_TOT + s0;
            #pragma unroll
            for (int r = 0; r < 16; r++) {
                int f  = tid + THREADS * r;        // float4 index 0..4095
                int c  = f >> 5;
                int s4 = (f & 31) << 2;
                float4 v = *(const float4*)(xb + (size_t)c * S_TOT + s4);
                float* d = Xs + c * XS_STRIDE + s4;
                d[0] = v.x; d[1] = v.y; d[2] = v.z; d[3] = v.w;
            }
        }
        __syncthreads();

        // ---- GEMM1: logits[k][s] = sum_c W[k][c] * X[c][s] ----
        float acc[8][4];
        #pragma unroll
        for (int j = 0; j < 8; j++)
            #pragma unroll
            for (int i = 0; i < 4; i++) acc[j][i] = 0.f;

        #pragma unroll 4
        for (int c = 0; c < C_DIM; c++) {
            float xv[4];
            #pragma unroll
            for (int i = 0; i < 4; i++) xv[i] = Xs[c * XS_STRIDE + l + 32 * i];
            #pragma unroll
            for (int j = 0; j < 8; j++) {
                float wv = Ws[(w + 8 * j) * C_DIM + c];
                #pragma unroll
                for (int i = 0; i < 4; i++) acc[j][i] = fmaf(wv, xv[i], acc[j][i]);
            }
        }
        #pragma unroll
        for (int j = 0; j < 8; j++)
            #pragma unroll
            for (int i = 0; i < 4; i++)
                Ls[(w + 8 * j) * LS_STRIDE + l + 32 * i] = acc[j][i];
        __syncthreads();

        // ---- softmax over k, one thread per pixel s ----
        if (tid < SC) {
            float m = -1e30f;
            #pragma unroll 4
            for (int k = 0; k < K_CL; k++) m = fmaxf(m, Ls[k * LS_STRIDE + tid]);
            float ssum = 0.f;
            #pragma unroll 4
            for (int k = 0; k < K_CL; k++) {
                float e = __expf(Ls[k * LS_STRIDE + tid] - m);
                Ls[k * LS_STRIDE + tid] = e;
                ssum += e;
            }
            float inv = 1.f / ssum;
            #pragma unroll 4
            for (int k = 0; k < K_CL; k++) Ls[k * LS_STRIDE + tid] *= inv;
        }
        __syncthreads();

        // ---- per-cluster assignment mass (read-only on Ls, overlaps GEMM2) ----
        if (tid < K_CL) {
            float a = 0.f;
            #pragma unroll 4
            for (int s = 0; s < SC; s++) a += Ls[tid * LS_STRIDE + s];
            asum += a;
        }

        // ---- GEMM2: vacc[k][c] += sum_s A[k][s] * X[c][s] ----
        #pragma unroll 4
        for (int s = 0; s < SC; s++) {
            float xv[4];
            #pragma unroll
            for (int i = 0; i < 4; i++) xv[i] = Xs[(l + 32 * i) * XS_STRIDE + s];
            #pragma unroll
            for (int j = 0; j < 8; j++) {
                float av = Ls[(w + 8 * j) * LS_STRIDE + s];
                #pragma unroll
                for (int i = 0; i < 4; i++) vacc[j][i] = fmaf(av, xv[i], vacc[j][i]);
            }
        }
        __syncthreads();   // protect Xs/Ls before next chunk overwrite
    }

    // ---- write deterministic partials ----
    float* vp = g_vpart + (size_t)(n * SPLIT + sp) * K_CL * C_DIM;
    #pragma unroll
    for (int j = 0; j < 8; j++)
        #pragma unroll
        for (int i = 0; i < 4; i++)
            vp[(w + 8 * j) * C_DIM + l + 32 * i] = vacc[j][i];
    if (tid < K_CL) g_apart[(n * SPLIT + sp) * K_CL + tid] = asum;
}

__global__ void __launch_bounds__(THREADS)
netvlad_finalize(const float* __restrict__ cent, float* __restrict__ out) {
    __shared__ float vbuf[K_CL * C_DIM];   // 32 KB intra-normalized vlad
    __shared__ float red[8];

    const int n   = blockIdx.x;
    const int tid = threadIdx.x;
    const int w   = tid >> 5, l = tid & 31;

    float gpart = 0.f;
    #pragma unroll
    for (int j = 0; j < 8; j++) {
        const int k = w + 8 * j;

        float as = 0.f;
        #pragma unroll
        for (int p = 0; p < SPLIT; p++) as += g_apart[(n * SPLIT + p) * K_CL + k];

        float4 v = make_float4(0.f, 0.f, 0.f, 0.f);
        #pragma unroll
        for (int p = 0; p < SPLIT; p++) {
            const float4* vp = (const float4*)(g_vpart +
                (size_t)(n * SPLIT + p) * K_CL * C_DIM + k * C_DIM);
            float4 t = vp[l];
            v.x += t.x; v.y += t.y; v.z += t.z; v.w += t.w;
        }
        float4 ct = ((const float4*)(cent + k * C_DIM))[l];
        v.x -= as * ct.x; v.y -= as * ct.y; v.z -= as * ct.z; v.w -= as * ct.w;

        float ss = v.x * v.x + v.y * v.y + v.z * v.z + v.w * v.w;
        #pragma unroll
        for (int o = 16; o; o >>= 1) ss += __shfl_xor_sync(0xffffffffu, ss, o);

        float inv = 1.f / fmaxf(sqrtf(ss), EPSV);
        v.x *= inv; v.y *= inv; v.z *= inv; v.w *= inv;
        ((float4*)(vbuf + k * C_DIM))[l] = v;
        gpart += v.x * v.x + v.y * v.y + v.z * v.z + v.w * v.w;
    }

    #pragma unroll
    for (int o = 16; o; o >>= 1) gpart += __shfl_xor_sync(0xffffffffu, gpart, o);
    if (l == 0) red[w] = gpart;
    __syncthreads();
    if (tid == 0) {
        float g = 0.f;
        #pragma unroll
        for (int i = 0; i < 8; i++) g += red[i];
        red[0] = 1.f / fmaxf(sqrtf(g), EPSV);
    }
    __syncthreads();
    const float ginv = red[0];

    float4*       ob = (float4*)(out + (size_t)n * K_CL * C_DIM);
    const float4* vb = (const float4*)vbuf;
    #pragma unroll
    for (int r = 0; r < 8; r++) {
        float4 v = vb[tid + THREADS * r];
        v.x *= ginv; v.y *= ginv; v.z *= ginv; v.w *= ginv;
        ob[tid + THREADS * r] = v;
    }
}

extern "C" void kernel_launch(void* const* d_in, const int* in_sizes, int n_in,
                              void* d_out, int out_size) {
    const float* x     = (const float*)d_in[0];
    const float* convw = (const float*)d_in[1];
    const float* cent  = (const float*)d_in[2];
    float*       out   = (float*)d_out;

    cudaFuncSetAttribute(netvlad_main,
                         cudaFuncAttributeMaxDynamicSharedMemorySize, SMEM_BYTES);
    netvlad_main<<<dim3(SPLIT, N_IMG), THREADS, SMEM_BYTES>>>(x, convw);
    netvlad_finalize<<<N_IMG, THREADS>>>(cent, out);
}

// round 4
// speedup vs baseline: 1.2277x; 1.2277x over previous
#include <cuda_runtime.h>
#include <math.h>

#define N_IMG   32
#define C_DIM   128
#define K_CL    64
#define S_TOT   12544
#define SC      128
#define NCHUNK  98          // S_TOT / SC
#define SPLIT   9
#define CPB     11          // ceil(NCHUNK / SPLIT)
#define THREADS 256
#define EPSV    1e-12f

#define XS_STRIDE 129       // odd -> conflict-free scalar row AND column access
#define LS_STRIDE 66        // even -> 8B-aligned k-pair LDS.64, 2-way on scalar (ok)
#define WT_STRIDE 66

// smem: 2 X buffers + Ls + Wt
#define SMEM_FLOATS (2 * C_DIM * XS_STRIDE + SC * LS_STRIDE + C_DIM * WT_STRIDE)
#define SMEM_BYTES  (SMEM_FLOATS * 4)

typedef unsigned long long ull;

__device__ float g_vpart[(size_t)N_IMG * SPLIT * K_CL * C_DIM];
__device__ float g_apart[N_IMG * SPLIT * K_CL];
__device__ float g_gsum[N_IMG * 8];

__device__ __forceinline__ ull ffma2(ull a, ull b, ull c) {
    ull d;
    asm("fma.rn.f32x2 %0, %1, %2, %3;" : "=l"(d) : "l"(a), "l"(b), "l"(c));
    return d;
}
__device__ __forceinline__ ull pack2(float lo, float hi) {
    ull d;
    asm("mov.b64 %0, {%1, %2};" : "=l"(d) : "f"(lo), "f"(hi));
    return d;
}
__device__ __forceinline__ void unpack2(ull v, float& lo, float& hi) {
    asm("mov.b64 {%0, %1}, %2;" : "=f"(lo), "=f"(hi) : "l"(v));
}
__device__ __forceinline__ void cp4(float* dst, const float* src) {
    unsigned ds = (unsigned)__cvta_generic_to_shared(dst);
    asm volatile("cp.async.ca.shared.global [%0], [%1], 4;" :: "r"(ds), "l"(src));
}
__device__ __forceinline__ void cp_commit() {
    asm volatile("cp.async.commit_group;");
}
template<int N> __device__ __forceinline__ void cp_wait() {
    asm volatile("cp.async.wait_group %0;" :: "n"(N));
}

// Prefetch one 128x128 x-chunk into an Xs buffer (stride 129).
// Thread t owns s = t&127, c = 2r + (t>>7): coalesced gmem, conflict-free smem.
__device__ __forceinline__ void prefetch_chunk(float* Xbuf, const float* xb) {
    const int t  = threadIdx.x;
    const int s  = t & 127;
    const int ch = t >> 7;                 // 0 or 1
    float*       d = Xbuf + (size_t)ch * XS_STRIDE + s;
    const float* g = xb   + (size_t)ch * S_TOT     + s;
    #pragma unroll
    for (int r = 0; r < 64; r++) {
        cp4(d, g);
        d += 2 * XS_STRIDE;
        g += 2 * S_TOT;
    }
}

__global__ void __launch_bounds__(THREADS, 1)
netvlad_main(const float* __restrict__ x, const float* __restrict__ convw) {
    extern __shared__ float sm[];
    float* X0 = sm;                                  // [128][129]
    float* X1 = X0 + C_DIM * XS_STRIDE;              // [128][129]
    float* Ls = X1 + C_DIM * XS_STRIDE;              // [128 s][66]  logits/probs [s][k]
    float* Wt = Ls + SC * LS_STRIDE;                 // [128 c][66]  W transposed [c][k]

    const int n   = blockIdx.y;
    const int sp  = blockIdx.x;
    const int tid = threadIdx.x;
    const int w   = tid >> 5;     // warp 0..7 -> k-pairs 4w+j (k = 8w+2j, +1)
    const int l   = tid & 31;     // lane      -> s/c = l + 32*i

    // ---- build Wt[c][k] from convw[k][c] (coalesced reads) ----
    for (int idx = tid; idx < K_CL * C_DIM; idx += THREADS) {
        int k = idx >> 7, c = idx & 127;
        Wt[c * WT_STRIDE + k] = convw[idx];
    }

    ull vacc[4][4];               // [j][i] vlad pairs {8w+2j, 8w+2j+1} at c=l+32i
    #pragma unroll
    for (int j = 0; j < 4; j++)
        #pragma unroll
        for (int i = 0; i < 4; i++) vacc[j][i] = 0ull;
    float asum = 0.f;

    const int chunk0 = sp * CPB;
    const int chunk1 = min(NCHUNK, chunk0 + CPB);
    const float* xb  = x + (size_t)n * C_DIM * S_TOT;

    prefetch_chunk(X0, xb + chunk0 * SC);
    cp_commit();
    __syncthreads();   // Wt ready (also before first use)

    for (int ch = chunk0; ch < chunk1; ch++) {
        float* Xb = ((ch - chunk0) & 1) ? X1 : X0;
        if (ch + 1 < chunk1) {
            float* Xn = ((ch + 1 - chunk0) & 1) ? X1 : X0;
            prefetch_chunk(Xn, xb + (ch + 1) * SC);
            cp_commit();
            cp_wait<1>();
        } else {
            cp_wait<0>();
        }
        __syncthreads();          // current buffer fully visible

        // ---- GEMM1: logit-pairs over k, vector over s ----
        {
            ull acc[4][4];
            #pragma unroll
            for (int j = 0; j < 4; j++)
                #pragma unroll
                for (int i = 0; i < 4; i++) acc[j][i] = 0ull;

            const float* xr = Xb + l;
            const float* wr = Wt + 8 * w;
            #pragma unroll 2
            for (int c = 0; c < C_DIM; c++) {
                ull wp[4];
                #pragma unroll
                for (int j = 0; j < 4; j++)
                    wp[j] = *(const ull*)(wr + 2 * j);      // broadcast {W[k][c],W[k+1][c]}
                ull xd[4];
                #pragma unroll
                for (int i = 0; i < 4; i++) {
                    float xv = xr[32 * i];
                    xd[i] = pack2(xv, xv);
                }
                #pragma unroll
                for (int j = 0; j < 4; j++)
                    #pragma unroll
                    for (int i = 0; i < 4; i++)
                        acc[j][i] = ffma2(wp[j], xd[i], acc[j][i]);
                xr += XS_STRIDE;
                wr += WT_STRIDE;
            }
            #pragma unroll
            for (int i = 0; i < 4; i++)
                #pragma unroll
                for (int j = 0; j < 4; j++)
                    *(ull*)(Ls + (l + 32 * i) * LS_STRIDE + 8 * w + 2 * j) = acc[j][i];
        }
        __syncthreads();

        // ---- softmax over k for each pixel s (threads 0..127) ----
        if (tid < SC) {
            float* row = Ls + tid * LS_STRIDE;
            float m = -1e30f;
            #pragma unroll 8
            for (int k = 0; k < K_CL; k++) m = fmaxf(m, row[k]);
            float ssm = 0.f;
            #pragma unroll 8
            for (int k = 0; k < K_CL; k++) {
                float e = __expf(row[k] - m);
                row[k] = e;
                ssm += e;
            }
            float inv = 1.f / ssm;
            #pragma unroll 8
            for (int k = 0; k < K_CL; k++) row[k] *= inv;
        }
        __syncthreads();

        // ---- per-cluster assignment mass ----
        if (tid < K_CL) {
            float a = 0.f;
            #pragma unroll 8
            for (int s = 0; s < SC; s++) a += Ls[s * LS_STRIDE + tid];
            asum += a;
        }

        // ---- GEMM2: vlad-pairs over k, vector over c ----
        {
            const float* xr = Xb + l * XS_STRIDE;   // + s per iter, rows 32*i apart
            const float* ar = Ls + 8 * w;
            #pragma unroll 2
            for (int s = 0; s < SC; s++) {
                ull ap[4];
                #pragma unroll
                for (int j = 0; j < 4; j++)
                    ap[j] = *(const ull*)(ar + 2 * j);  // broadcast prob pair
                ull xd[4];
                #pragma unroll
                for (int i = 0; i < 4; i++) {
                    float xv = xr[(size_t)(32 * i) * XS_STRIDE];
                    xd[i] = pack2(xv, xv);
                }
                #pragma unroll
                for (int j = 0; j < 4; j++)
                    #pragma unroll
                    for (int i = 0; i < 4; i++)
                        vacc[j][i] = ffma2(ap[j], xd[i], vacc[j][i]);
                xr += 1;
                ar += LS_STRIDE;
            }
        }
        __syncthreads();   // protect Ls + prefetch target buffer
    }

    // ---- write deterministic partials ----
    float* vp = g_vpart + (size_t)(n * SPLIT + sp) * K_CL * C_DIM;
    #pragma unroll
    for (int j = 0; j < 4; j++) {
        const int k0 = 8 * w + 2 * j;
        #pragma unroll
        for (int i = 0; i < 4; i++) {
            float lo, hi;
            unpack2(vacc[j][i], lo, hi);
            vp[(k0 + 0) * C_DIM + l + 32 * i] = lo;
            vp[(k0 + 1) * C_DIM + l + 32 * i] = hi;
        }
    }
    if (tid < K_CL) g_apart[(n * SPLIT + sp) * K_CL + tid] = asum;
}

// reduce partials, subtract a*cent, intra-normalize, write out, per-group sumsq
__global__ void __launch_bounds__(THREADS)
netvlad_reduce(const float* __restrict__ cent, float* __restrict__ out) {
    __shared__ float red[8];
    const int n   = blockIdx.y;
    const int kg  = blockIdx.x;          // 0..7
    const int tid = threadIdx.x;
    const int w   = tid >> 5, l = tid & 31;
    const int k   = kg * 8 + w;

    float as = 0.f;
    #pragma unroll
    for (int p = 0; p < SPLIT; p++) as += g_apart[(n * SPLIT + p) * K_CL + k];

    float4 v = make_float4(0.f, 0.f, 0.f, 0.f);
    #pragma unroll
    for (int p = 0; p < SPLIT; p++) {
        const float4* vp = (const float4*)(g_vpart +
            (size_t)(n * SPLIT + p) * K_CL * C_DIM + k * C_DIM);
        float4 t = vp[l];
        v.x += t.x; v.y += t.y; v.z += t.z; v.w += t.w;
    }
    float4 ct = ((const float4*)(cent + k * C_DIM))[l];
    v.x -= as * ct.x; v.y -= as * ct.y; v.z -= as * ct.z; v.w -= as * ct.w;

    float ss = v.x * v.x + v.y * v.y + v.z * v.z + v.w * v.w;
    #pragma unroll
    for (int o = 16; o; o >>= 1) ss += __shfl_xor_sync(0xffffffffu, ss, o);
    float inv = 1.f / fmaxf(sqrtf(ss), EPSV);
    v.x *= inv; v.y *= inv; v.z *= inv; v.w *= inv;
    ((float4*)(out + (size_t)n * K_CL * C_DIM + k * C_DIM))[l] = v;

    if (l == 0) red[w] = ss * inv * inv;   // sumsq of normalized row
    __syncthreads();
    if (tid == 0) {
        float g = 0.f;
        #pragma unroll
        for (int i = 0; i < 8; i++) g += red[i];
        g_gsum[n * 8 + kg] = g;
    }
}

__global__ void __launch_bounds__(THREADS)
netvlad_scale(float* __restrict__ out) {
    const int n   = blockIdx.x;
    const int tid = threadIdx.x;
    float g = 0.f;
    #pragma unroll
    for (int i = 0; i < 8; i++) g += g_gsum[n * 8 + i];
    const float ginv = 1.f / fmaxf(sqrtf(g), EPSV);

    float4* ob = (float4*)(out + (size_t)n * K_CL * C_DIM);
    #pragma unroll
    for (int r = 0; r < 8; r++) {
        float4 v = ob[tid + THREADS * r];
        v.x *= ginv; v.y *= ginv; v.z *= ginv; v.w *= ginv;
        ob[tid + THREADS * r] = v;
    }
}

extern "C" void kernel_launch(void* const* d_in, const int* in_sizes, int n_in,
                              void* d_out, int out_size) {
    const float* x     = (const float*)d_in[0];
    const float* convw = (const float*)d_in[1];
    const float* cent  = (const float*)d_in[2];
    float*       out   = (float*)d_out;

    cudaFuncSetAttribute(netvlad_main,
                         cudaFuncAttributeMaxDynamicSharedMemorySize, SMEM_BYTES);
    netvlad_main<<<dim3(SPLIT, N_IMG), THREADS, SMEM_BYTES>>>(x, convw);
    netvlad_reduce<<<dim3(8, N_IMG), THREADS>>>(cent, out);
    netvlad_scale<<<N_IMG, THREADS>>>(out);
}